// round 8
// baseline (speedup 1.0000x reference)
#include <cuda_runtime.h>

// ---------------------------------------------------------------------------
// SimpleYOLOLoss on GB300 — single fused kernel, single wave (416 blocks).
//  - target phase: 256 blocks; each warp handles FOUR same-level items
//    (same (b, lvl), 4 consecutive targets) -> MLP 8 gathers/lane,
//    12 pipelined shuffle chains, one epilogue per 4 items.
//  - cls phase: 160 streaming blocks (L0: 128 blocks/16 iters; one block per
//    batch covers L1+L2+L3).
//  - last-block finalize + reset (graph-replay safe).
// ---------------------------------------------------------------------------

#define FULL_MASK 0xffffffffu

static constexpr int BATCH = 32;
static constexpr int NTGT  = 64;

static constexpr int TGT_BLOCKS = 256;        // 32 items/block, 4 per warp
static constexpr int CLS_BLOCKS = 128 + 32;   // L0 + combined(L1,L2,L3)
static constexpr int TOTAL_BLOCKS = TGT_BLOCKS + CLS_BLOCKS;  // 416

__device__ double       g_S[BATCH];   // per-batch sum over levels of base mean
__device__ int          g_cnt[BATCH]; // valid targets per batch
__device__ double       g_adj;
__device__ double       g_box;
__device__ double       g_dfl;
__device__ unsigned int g_arrive;

__global__ void __launch_bounds__(256) yolo_fused_kernel(
    const float* __restrict__ c0, const float* __restrict__ c1,
    const float* __restrict__ c2, const float* __restrict__ c3,
    const float* __restrict__ r0, const float* __restrict__ r1,
    const float* __restrict__ r2, const float* __restrict__ r3,
    const float* __restrict__ tg,
    float* __restrict__ out)
{
    const int tid = threadIdx.x;

    if (blockIdx.x < TGT_BLOCKS) {
        // ------------- per-target term: 4 same-level items per warp -------
        __shared__ double s_acc[3];
        __shared__ int    s_cnt;
        if (tid < 3) s_acc[tid] = 0.0;
        if (tid == 3) s_cnt = 0;
        __syncthreads();

        const int w    = tid >> 5;
        const int lane = tid & 31;
        const int bi   = blockIdx.x;
        const int b    = bi >> 3;                      // 8 blocks per batch
        const int lvl  = w & 3;
        const int n0   = ((bi & 7) << 3) + ((w >> 2) << 2);  // warp's 4 targets

        const float s     = (float)(8 << lvl);
        const float inv_s = 1.0f / s;                  // exact (power of two)
        const int   Wl    = 128 >> lvl;
        const int   HW    = Wl * Wl;
        const float invHW = 1.0f / (float)HW;          // exact (power of two)
        const float* cp = (lvl == 0) ? c0 : (lvl == 1) ? c1 : (lvl == 2) ? c2 : c3;
        const float* rp = (lvl == 0) ? r0 : (lvl == 1) ? r1 : (lvl == 2) ? r2 : r3;
        const float* rB = rp + (size_t)b * 64 * HW;

        // ---- load 4 targets; derive everything cheap ----
        bool  valid[4];
        int   cid[4], cell[4];
        float tr0[4], tr1[4], tr2[4], tr3[4];
        const float* tp = tg + (size_t)(b * NTGT + n0) * 5;
        #pragma unroll
        for (int j = 0; j < 4; j++) {
            float t0 = tp[j * 5 + 0];
            float x1 = tp[j * 5 + 1], y1 = tp[j * 5 + 2];
            float x2 = tp[j * 5 + 3], y2 = tp[j * 5 + 4];
            valid[j] = (t0 >= 0.0f);
            cid[j]   = (int)fmaxf(t0, 0.0f);
            float cx = (x1 + x2) * 0.5f, cy = (y1 + y2) * 0.5f;
            int gx = min(max((int)(cx * inv_s), 0), Wl - 1);
            int gy = min(max((int)(cy * inv_s), 0), Wl - 1);
            if (!valid[j]) { gx = 0; gy = 0; }         // safe address
            cell[j] = gy * Wl + gx;
            tr0[j] = (cx - (float)gx * s) * inv_s;
            tr1[j] = (cy - (float)gy * s) * inv_s;
            tr2[j] = (x2 - x1) * inv_s;
            tr3[j] = (y2 - y1) * inv_s;
        }

        // ---- issue all 8 gathers (MLP 8) ----
        float p0[4], p1[4];
        #pragma unroll
        for (int j = 0; j < 4; j++) {
            const float* rb = rB + cell[j];
            p0[j] = rb[(size_t)lane * HW];
            p1[j] = rb[(size_t)(lane + 32) * HW];
        }

        // ---- adj logits: lanes 0..3 each own one item (parallel loads) ----
        float adjv = 0.0f;
        if (lane < 4) {
            int j = lane;
            const float* lp = cp + ((size_t)b * HW + (size_t)cell[j]) * 4;
            float l0 = lp[0];
            float lc = lp[cid[j]];
            adjv = valid[j] ? (l0 - lc) * invHW : 0.0f;
        }

        // ---- dfl chains (4 independent, pipelined) ----
        float d[4];
        #pragma unroll
        for (int j = 0; j < 4; j++) {
            float sa = (lane < 16) ? tr0[j] : tr1[j];
            float sb = (lane < 16) ? tr2[j] : tr3[j];
            d[j] = fabsf(p0[j] - sa) + fabsf(p1[j] - sb);
        }
        #pragma unroll
        for (int o = 16; o > 0; o >>= 1) {
            #pragma unroll
            for (int j = 0; j < 4; j++)
                d[j] += __shfl_xor_sync(FULL_MASK, d[j], o);
        }

        // ---- 16-lane segmented sums (8 independent chains) ----
        float q0[4], q1[4];
        #pragma unroll
        for (int j = 0; j < 4; j++) { q0[j] = p0[j]; q1[j] = p1[j]; }
        #pragma unroll
        for (int o = 8; o > 0; o >>= 1) {
            #pragma unroll
            for (int j = 0; j < 4; j++) {
                q0[j] += __shfl_xor_sync(FULL_MASK, q0[j], o);
                q1[j] += __shfl_xor_sync(FULL_MASK, q1[j], o);
            }
        }
        float m1[4], m3[4];
        #pragma unroll
        for (int j = 0; j < 4; j++) {
            m1[j] = __shfl_sync(FULL_MASK, q0[j], 16);
            m3[j] = __shfl_sync(FULL_MASK, q1[j], 16);
        }

        // gather adj contributions from lanes 0..3 into lane 0
        adjv += __shfl_xor_sync(FULL_MASK, adjv, 1);
        adjv += __shfl_xor_sync(FULL_MASK, adjv, 2);

        if (lane == 0) {
            const float i16 = 1.0f / 16.0f;
            float box = 0.0f, dfl = 0.0f;
            int   cnt = 0;
            #pragma unroll
            for (int j = 0; j < 4; j++) {
                if (valid[j]) {
                    box += (fabsf(q0[j] * i16 - tr0[j]) + fabsf(m1[j] * i16 - tr1[j]) +
                            fabsf(q1[j] * i16 - tr2[j]) + fabsf(m3[j] * i16 - tr3[j])) * 0.25f;
                    dfl += d[j] * (1.0f / 64.0f);
                    cnt++;
                }
            }
            if (cnt) {
                atomicAdd(&s_acc[0], (double)adjv);
                atomicAdd(&s_acc[1], (double)box);
                atomicAdd(&s_acc[2], (double)dfl);
                if (lvl == 0) atomicAdd(&s_cnt, cnt);
            }
        }
        __syncthreads();
        if (tid == 0) {
            atomicAdd(&g_adj, s_acc[0]);
            atomicAdd(&g_box, s_acc[1]);
            atomicAdd(&g_dfl, s_acc[2]);
            if (s_cnt) atomicAdd(&g_cnt[b], s_cnt);
        }
    } else {
        // ------------------- cls base term (streaming, as R6) -------------
        int cb = blockIdx.x - TGT_BLOCKS;

        auto rowval = [](const float4 v) -> float {
            float m  = fmaxf(fmaxf(v.x, v.y), fmaxf(v.z, v.w));
            float se = __expf(v.x - m) + __expf(v.y - m) +
                       __expf(v.z - m) + __expf(v.w - m);
            return (m + __logf(se)) - v.x;
        };

        float scaled;
        int b;
        if (cb < 128) {
            b = cb >> 2;
            const float4* base = reinterpret_cast<const float4*>(c0) +
                                 (size_t)b * 16384 + (size_t)(cb & 3) * 4096 + tid;
            float acc = 0.0f;
            #pragma unroll
            for (int i = 0; i < 16; i++)
                acc += rowval(base[(size_t)i * 256]);
            scaled = acc * (1.0f / 16384.0f);
        } else {
            b = cb - 128;
            const float4* b1 = reinterpret_cast<const float4*>(c1) + (size_t)b * 4096 + tid;
            const float4* b2 = reinterpret_cast<const float4*>(c2) + (size_t)b * 1024 + tid;
            const float4* b3 = reinterpret_cast<const float4*>(c3) + (size_t)b * 256  + tid;
            float a1 = 0.0f, a2 = 0.0f, a3;
            #pragma unroll
            for (int i = 0; i < 16; i++)
                a1 += rowval(b1[(size_t)i * 256]);
            #pragma unroll
            for (int i = 0; i < 4; i++)
                a2 += rowval(b2[(size_t)i * 256]);
            a3 = rowval(b3[0]);
            scaled = a1 * (1.0f / 4096.0f) + a2 * (1.0f / 1024.0f)
                   + a3 * (1.0f / 256.0f);
        }

        #pragma unroll
        for (int o = 16; o > 0; o >>= 1)
            scaled += __shfl_xor_sync(FULL_MASK, scaled, o);

        __shared__ float wsum[8];
        int wid = tid >> 5;
        if ((tid & 31) == 0) wsum[wid] = scaled;
        __syncthreads();
        if (tid == 0) {
            double ssum = 0.0;
            #pragma unroll
            for (int i = 0; i < 8; i++) ssum += (double)wsum[i];
            atomicAdd(&g_S[b], ssum);
        }
    }

    // ------------------- last-block finalize + reset -------------------
    __shared__ bool is_last;
    __threadfence();
    if (tid == 0) {
        unsigned int v = atomicAdd(&g_arrive, 1u);
        is_last = (v == (unsigned)(TOTAL_BLOCKS - 1));
    }
    __syncthreads();

    if (is_last) {
        __threadfence();   // acquire: see all other blocks' accumulator writes
        if (tid == 0) {
            double cls = g_adj;
            #pragma unroll
            for (int b2 = 0; b2 < BATCH; b2++)
                cls += (double)g_cnt[b2] * g_S[b2];
            float clsf = (float)cls;
            float boxf = (float)g_box;
            float dflf = (float)g_dfl;
            out[0] = 0.3f * clsf + 8.0f * boxf + 1.5f * dflf;
            out[1] = clsf;
            out[2] = boxf;
            out[3] = dflf;
        }
        __syncthreads();   // output computed before anyone resets state
        if (tid < BATCH)     { g_S[tid] = 0.0; g_cnt[tid] = 0; }
        if (tid == BATCH)      g_adj = 0.0;
        if (tid == BATCH + 1)  g_box = 0.0;
        if (tid == BATCH + 2)  g_dfl = 0.0;
        if (tid == BATCH + 3)  g_arrive = 0u;
    }
}

extern "C" void kernel_launch(void* const* d_in, const int* in_sizes, int n_in,
                              void* d_out, int out_size)
{
    // Map inputs by element count (order-agnostic). Ambiguous pairs resolved
    // by first-occurrence (cls precedes its reg twin in both grouped and
    // interleaved metadata orders).
    const float *c0 = nullptr, *c1 = nullptr, *c2 = nullptr, *c3 = nullptr;
    const float *r0 = nullptr, *r1 = nullptr, *r2 = nullptr, *r3 = nullptr;
    const float *tg = nullptr;
    int seen2097152 = 0, seen524288 = 0;

    for (int i = 0; i < n_in; i++) {
        const float* p = (const float*)d_in[i];
        switch (in_sizes[i]) {
            case 33554432: r0 = p; break;
            case 8388608:  r1 = p; break;
            case 131072:   c2 = p; break;
            case 32768:    c3 = p; break;
            case 10240:    tg = p; break;
            case 2097152:
                if (seen2097152++ == 0) c0 = p; else r2 = p;
                break;
            case 524288:
                if (seen524288++ == 0) c1 = p; else r3 = p;
                break;
            default: break;
        }
    }

    float* out = (float*)d_out;
    yolo_fused_kernel<<<TOTAL_BLOCKS, 256>>>(c0, c1, c2, c3,
                                             r0, r1, r2, r3, tg, out);
}